// round 10
// baseline (speedup 1.0000x reference)
#include <cuda_runtime.h>
#include <math.h>
#include <stdint.h>

#define LSEQ 1024
#define BATCH 8
#define HDIM 300
#define NC 11234
#define W1COLS 650
#define NPAIR (BATCH * NC)

// ---------------- device scratch ----------------
__device__ __align__(16) float g_A[BATCH * LSEQ * HDIM];
__device__ __align__(16) float g_C[BATCH * LSEQ * HDIM];
__device__ __align__(16) float g_T2[11 * HDIM];

// ---------------- GEMM: 3-stage cp.async tf32, K-concat (he then h_share) ----
// grid.z = 0: (h_e || h_share) @ W1[:,0:300]^T   -> g_A
// grid.z = 1: (h_c || h_share) @ W1[:,300:600]^T -> g_C
// grid.z = 2: blocks y<13 compute T2 table (3300 outputs), others exit
#define GBM 128
#define GBN 64
#define GBK 16
#define KSTR 20
#define NIT_H 19          // tiles per 300-k half (last tile zero-padded)
#define NIT_TOT 38
#define NSTG 3

__device__ __forceinline__ void cp_async16(uint32_t dst, const void* src, int src_bytes) {
    asm volatile("cp.async.cg.shared.global [%0], [%1], 16, %2;\n"
                 :: "r"(dst), "l"(src), "r"(src_bytes));
}
__device__ __forceinline__ void cp_async8(uint32_t dst, const void* src, int src_bytes) {
    asm volatile("cp.async.ca.shared.global [%0], [%1], 8, %2;\n"
                 :: "r"(dst), "l"(src), "r"(src_bytes));
}

__global__ __launch_bounds__(256) void gemm_tf32_kernel(
    const float* __restrict__ h_e, const float* __restrict__ h_c,
    const float* __restrict__ h_share, const float* __restrict__ W1,
    const float* __restrict__ posW, const float* __restrict__ b1)
{
    __shared__ __align__(16) float As[NSTG][GBM][KSTR];
    __shared__ __align__(16) float Bs[NSTG][GBN][KSTR];

    const int z = blockIdx.z;
    const int tid = threadIdx.x;

    // ---------- z == 2: T2 table side-job ----------
    if (z == 2) {
        if (blockIdx.y >= 13 || blockIdx.x != 0) return;
        // reuse As as scratch: posW copy (550) + M matrix (550)
        float* sPW = &As[0][0][0];        // 550 floats
        float* sM  = &As[0][0][0] + 576;  // 550 floats
        for (int q = tid; q < 550; q += 256) sPW[q] = posW[q];
        __syncthreads();
        for (int q = tid; q < 550; q += 256) {
            int r = q / 50, d = q - r * 50;
            float acc = 0.f;
#pragma unroll
            for (int rp = 0; rp < 11; rp++) {
                float dd = (float)(r - rp);
                int aa = rp - 5; if (aa < 0) aa = -aa;
                acc += (float)(LSEQ - aa) * expf(-dd * dd) * sPW[rp * 50 + d];
            }
            sM[q] = acc;
        }
        __syncthreads();
        int gid = blockIdx.y * 256 + tid;
        if (gid < 11 * HDIM) {
            int r = gid / HDIM, h = gid - r * HDIM;
            float acc = b1[h];
            const float* w1row = W1 + h * W1COLS + 600;
            const float* m = sM + r * 50;
#pragma unroll
            for (int d = 0; d < 50; d++) acc += m[d] * w1row[d];
            g_T2[gid] = acc;
        }
        return;
    }

    // ---------- GEMM path ----------
    const float* X = z ? h_c : h_e;
    const int off = z ? 300 : 0;
    float* Out = z ? g_C : g_A;

    const int m0 = blockIdx.y * GBM;
    const int n0 = blockIdx.x * GBN;
    const int warp = tid >> 5;
    const int lane = tid & 31;
    const int wm = (warp & 3) * 32;
    const int wn = (warp >> 2) * 32;
    const int lq = lane >> 2;
    const int lr = lane & 3;

    const int arow = tid >> 2;
    const int ak   = (tid & 3) * 4;
    const int brow = tid >> 3;
    const int bk   = 2 * (tid & 7);

    const float* eSrc0 = X + (m0 + arow) * HDIM + ak;
    const float* eSrc1 = X + (m0 + arow + 64) * HDIM + ak;
    const float* sSrc0 = h_share + (m0 + arow) * HDIM + ak;
    const float* sSrc1 = h_share + (m0 + arow + 64) * HDIM + ak;
    const float* bSrc0 = W1 + (n0 + brow) * W1COLS + off + bk;
    const float* bSrc1 = W1 + (n0 + brow + 32) * W1COLS + off + bk;
    const bool bOk0 = (n0 + brow) < HDIM;
    const bool bOk1 = (n0 + brow + 32) < HDIM;

    const uint32_t aD0 = (uint32_t)__cvta_generic_to_shared(&As[0][arow][ak]);
    const uint32_t aD1 = (uint32_t)__cvta_generic_to_shared(&As[0][arow + 64][ak]);
    const uint32_t bD0 = (uint32_t)__cvta_generic_to_shared(&Bs[0][brow][bk]);
    const uint32_t bD1 = (uint32_t)__cvta_generic_to_shared(&Bs[0][brow + 32][bk]);
    const uint32_t aBufSz = GBM * KSTR * 4;
    const uint32_t bBufSz = GBN * KSTR * 4;

    float acc[2][4][4];
#pragma unroll
    for (int a = 0; a < 2; a++)
#pragma unroll
        for (int b = 0; b < 4; b++)
#pragma unroll
            for (int c = 0; c < 4; c++) acc[a][b][c] = 0.f;

    auto issue = [&](int stage, int it) {
        int half = (it >= NIT_H);
        int k0 = (it - half * NIT_H) * GBK;
        const float* a0 = half ? sSrc0 : eSrc0;
        const float* a1 = half ? sSrc1 : eSrc1;
        int asz = ((k0 + ak) < HDIM) ? 16 : 0;
        cp_async16(aD0 + stage * aBufSz, a0 + k0, asz);
        cp_async16(aD1 + stage * aBufSz, a1 + k0, asz);
        bool kOk = (k0 + bk) < HDIM;
        cp_async8(bD0 + stage * bBufSz, bSrc0 + k0, (bOk0 && kOk) ? 8 : 0);
        cp_async8(bD1 + stage * bBufSz, bSrc1 + k0, (bOk1 && kOk) ? 8 : 0);
    };

    issue(0, 0);
    asm volatile("cp.async.commit_group;\n" ::: "memory");
    issue(1, 1);
    asm volatile("cp.async.commit_group;\n" ::: "memory");

    int buf = 0;
    for (int it = 0; it < NIT_TOT; it++) {
        asm volatile("cp.async.wait_group 1;\n" ::: "memory");
        __syncthreads();

        int nx = it + 2;
        if (nx < NIT_TOT) issue(nx % NSTG, nx);
        asm volatile("cp.async.commit_group;\n" ::: "memory");

#pragma unroll
        for (int s = 0; s < 2; s++) {
            const int kb = s * 8 + lr;
            unsigned af[2][4];
#pragma unroll
            for (int mf = 0; mf < 2; mf++) {
                const int mrow = wm + mf * 16 + lq;
                af[mf][0] = __float_as_uint(As[buf][mrow][kb]);
                af[mf][1] = __float_as_uint(As[buf][mrow + 8][kb]);
                af[mf][2] = __float_as_uint(As[buf][mrow][kb + 4]);
                af[mf][3] = __float_as_uint(As[buf][mrow + 8][kb + 4]);
            }
            unsigned bf[4][2];
#pragma unroll
            for (int nf = 0; nf < 4; nf++) {
                const int nrow = wn + nf * 8 + lq;
                bf[nf][0] = __float_as_uint(Bs[buf][nrow][kb]);
                bf[nf][1] = __float_as_uint(Bs[buf][nrow][kb + 4]);
            }
#pragma unroll
            for (int mf = 0; mf < 2; mf++)
#pragma unroll
                for (int nf = 0; nf < 4; nf++) {
                    asm volatile(
                        "mma.sync.aligned.m16n8k8.row.col.f32.tf32.tf32.f32 "
                        "{%0,%1,%2,%3}, {%4,%5,%6,%7}, {%8,%9}, {%0,%1,%2,%3};\n"
                        : "+f"(acc[mf][nf][0]), "+f"(acc[mf][nf][1]),
                          "+f"(acc[mf][nf][2]), "+f"(acc[mf][nf][3])
                        : "r"(af[mf][0]), "r"(af[mf][1]), "r"(af[mf][2]), "r"(af[mf][3]),
                          "r"(bf[nf][0]), "r"(bf[nf][1]));
                }
        }
        buf = (buf + 1 == NSTG) ? 0 : buf + 1;
    }

#pragma unroll
    for (int mf = 0; mf < 2; mf++) {
        const int row = m0 + wm + mf * 16 + lq;
#pragma unroll
        for (int nf = 0; nf < 4; nf++) {
            const int col = n0 + wn + nf * 8 + 2 * lr;
            if (col < HDIM) {
                *(float2*)&Out[row * HDIM + col] =
                    make_float2(acc[mf][nf][0], acc[mf][nf][1]);
                *(float2*)&Out[(row + 8) * HDIM + col] =
                    make_float2(acc[mf][nf][2], acc[mf][nf][3]);
            }
        }
    }
}

// ---------------- epilogue: i-tiled, 16-lane segments (R9 known-good) ----------------
#define CHI 8

__device__ __forceinline__ int band_off(int i) {
    if (i <= 1019) return (i < 5) ? (i * i + 11 * i) / 2 : 11 * i - 15;
    int s = i - 1019;
    return 11194 + 10 * s - s * (s - 1) / 2;
}

__global__ __launch_bounds__(256) void epi_kernel(
    const float* __restrict__ lng, const float* __restrict__ lnb,
    const float* __restrict__ W2, const float* __restrict__ b2,
    float* __restrict__ out, int write_pos)
{
    __shared__ __align__(16) float s_g[304];
    __shared__ __align__(16) float s_b[304];
    __shared__ __align__(16) float s_w[304];
    __shared__ __align__(16) float sT2[11 * HDIM];
    __shared__ __align__(16) float sA[CHI * HDIM];
    __shared__ __align__(16) float sC[(CHI + 10) * HDIM];

    const int tid = threadIdx.x;
    const int i0 = blockIdx.x * CHI;
    const int b = blockIdx.y;

    for (int h = tid; h < HDIM; h += 256) {
        s_g[h] = lng[h]; s_b[h] = lnb[h]; s_w[h] = W2[h];
    }
    for (int q = tid; q < 11 * HDIM / 4; q += 256)
        ((float4*)sT2)[q] = ((const float4*)g_T2)[q];
    {
        const float4* src = (const float4*)(g_A + (b * LSEQ + i0) * HDIM);
        float4* dst = (float4*)sA;
        for (int q = tid; q < CHI * (HDIM / 4); q += 256) dst[q] = src[q];
    }
    const int j0c = (i0 - 5 < 0) ? 0 : i0 - 5;
    const int j1c = (i0 + CHI + 4 > LSEQ - 1) ? LSEQ - 1 : i0 + CHI + 4;
    const int ncr = j1c - j0c + 1;
    {
        const float4* src = (const float4*)(g_C + (b * LSEQ + j0c) * HDIM);
        float4* dst = (float4*)sC;
        for (int q = tid; q < ncr * (HDIM / 4); q += 256) dst[q] = src[q];
    }
    __syncthreads();

    const int warp = tid >> 5;
    const int lane = tid & 31;
    const int half = lane >> 4;
    const int l16 = lane & 15;
    const float bias = __ldg(b2);
    const float inv = 1.f / (float)HDIM;

    for (int it = 0; it < 6; it++) {
        int p = it * 16 + warp * 2 + half;
        bool pv = (p < 88);
        int pc = pv ? p : 0;
        int i_off = pc / 11;
        int rel = pc - i_off * 11 - 5;
        int i = i0 + i_off;
        int j = i + rel;
        pv = pv && (j >= 0) && (j < LSEQ);

        const float4* a4 = (const float4*)(sA + i_off * HDIM);
        const float4* c4 = (const float4*)(sC + (pv ? (j - j0c) : 0) * HDIM);
        const float4* t4 = (const float4*)(sT2 + (rel + 5) * HDIM);

        float s1 = 0.f, s2 = 0.f;
#pragma unroll
        for (int q = 0; q < 5; q++) {
            int f = q * 16 + l16;
            if (f < 75) {
                float4 a = a4[f], c = c4[f], t = t4[f];
                float x0 = a.x + c.x + t.x, x1 = a.y + c.y + t.y;
                float x2 = a.z + c.z + t.z, x3 = a.w + c.w + t.w;
                s1 += x0 + x1 + x2 + x3;
                s2 += x0 * x0 + x1 * x1 + x2 * x2 + x3 * x3;
            }
        }
#pragma unroll
        for (int o = 8; o; o >>= 1) {
            s1 += __shfl_xor_sync(0xffffffffu, s1, o);
            s2 += __shfl_xor_sync(0xffffffffu, s2, o);
        }
        float mu = s1 * inv;
        float var = s2 * inv - mu * mu;
        float rstd = rsqrtf(var + 1e-5f);

        float dot = 0.f;
#pragma unroll
        for (int q = 0; q < 5; q++) {
            int f = q * 16 + l16;
            if (f < 75) {
                float4 a = a4[f], c = c4[f], t = t4[f];
                float4 g = *(const float4*)&s_g[f * 4];
                float4 bb = *(const float4*)&s_b[f * 4];
                float4 w = *(const float4*)&s_w[f * 4];
                float xe[4] = {a.x + c.x + t.x, a.y + c.y + t.y,
                               a.z + c.z + t.z, a.w + c.w + t.w};
                float ge[4] = {g.x, g.y, g.z, g.w};
                float be[4] = {bb.x, bb.y, bb.z, bb.w};
                float we[4] = {w.x, w.y, w.z, w.w};
#pragma unroll
                for (int e = 0; e < 4; e++) {
                    float y = (xe[e] - mu) * rstd * ge[e] + be[e];
                    y = (y > 0.f) ? y : (__expf(y) - 1.f);
                    dot += y * we[e];
                }
            }
        }
#pragma unroll
        for (int o = 8; o; o >>= 1) dot += __shfl_xor_sync(0xffffffffu, dot, o);

        if (pv && l16 == 0) {
            int jlo = (i - 5 < 0) ? 0 : i - 5;
            int oidx = band_off(i) + (j - jlo);
            out[b * NC + oidx] = dot + bias;
            if (write_pos && b == 0) {
                out[NPAIR + 2 * oidx]     = (float)(i + 1);
                out[NPAIR + 2 * oidx + 1] = (float)(j + 1);
            }
        }
    }
}

// ---------------- launcher ----------------
extern "C" void kernel_launch(void* const* d_in, const int* in_sizes, int n_in,
                              void* d_out, int out_size) {
    const float* h_e     = (const float*)d_in[0];
    const float* h_c     = (const float*)d_in[1];
    const float* h_share = (const float*)d_in[2];
    const float* pos_W   = (const float*)d_in[4];
    const float* W1      = (const float*)d_in[5];
    const float* b1      = (const float*)d_in[6];
    const float* ln_g    = (const float*)d_in[7];
    const float* ln_b    = (const float*)d_in[8];
    const float* W2      = (const float*)d_in[9];
    const float* b2      = (const float*)d_in[10];
    float* out = (float*)d_out;

    // z=0: A-gemm, z=1: C-gemm, z=2: T2 side-job (13 blocks active)
    dim3 ggrid((HDIM + GBN - 1) / GBN, (BATCH * LSEQ) / GBM, 3);
    gemm_tf32_kernel<<<ggrid, 256>>>(h_e, h_c, h_share, W1, pos_W, b1);

    int write_pos = (out_size >= NPAIR + 2 * NC) ? 1 : 0;
    dim3 egrid(LSEQ / CHI, BATCH);
    epi_kernel<<<egrid, 256>>>(ln_g, ln_b, W2, b2, out, write_pos);
}

// round 11
// speedup vs baseline: 1.2716x; 1.2716x over previous
#include <cuda_runtime.h>
#include <math.h>
#include <stdint.h>

#define LSEQ 1024
#define BATCH 8
#define HDIM 300
#define NC 11234
#define W1COLS 650
#define NPAIR (BATCH * NC)

// ---------------- device scratch ----------------
__device__ __align__(16) float g_A[BATCH * LSEQ * HDIM];
__device__ __align__(16) float g_C[BATCH * LSEQ * HDIM];
__device__ __align__(16) float g_He[BATCH * LSEQ * HDIM];
__device__ __align__(16) float g_Hc[BATCH * LSEQ * HDIM];
__device__ __align__(16) float g_T2[11 * HDIM];

// ---------------- packed f32x2 helpers (sm_103a) ----------------
__device__ __forceinline__ uint64_t f2pk(float lo, float hi) {
    uint64_t r; asm("mov.b64 %0,{%1,%2};" : "=l"(r) : "f"(lo), "f"(hi)); return r;
}
__device__ __forceinline__ void f2up(uint64_t v, float& lo, float& hi) {
    asm("mov.b64 {%0,%1},%2;" : "=f"(lo), "=f"(hi) : "l"(v));
}
__device__ __forceinline__ uint64_t addx2(uint64_t a, uint64_t b) {
    uint64_t r; asm("add.rn.f32x2 %0,%1,%2;" : "=l"(r) : "l"(a), "l"(b)); return r;
}
__device__ __forceinline__ uint64_t fmax2(uint64_t a, uint64_t b, uint64_t c) {
    uint64_t r; asm("fma.rn.f32x2 %0,%1,%2,%3;" : "=l"(r) : "l"(a), "l"(b), "l"(c)); return r;
}

// ---------------- prep: adds (2 float4/thread, wide grid) + T2 table ----------------
__global__ __launch_bounds__(256) void prep_kernel(
    const float* __restrict__ h_e, const float* __restrict__ h_c,
    const float* __restrict__ h_share,
    const float* __restrict__ posW, const float* __restrict__ W1,
    const float* __restrict__ b1)
{
    const int tid = threadIdx.x;
    // N4 = 614400 = 1200 blocks * 512 float4 — exact
    const int t0 = blockIdx.x * 512 + tid;
    float4 s[2], a[2], c[2];
#pragma unroll
    for (int k = 0; k < 2; k++) {
        int idx = t0 + k * 256;
        s[k] = ((const float4*)h_share)[idx];
        a[k] = ((const float4*)h_e)[idx];
        c[k] = ((const float4*)h_c)[idx];
    }
#pragma unroll
    for (int k = 0; k < 2; k++) {
        int idx = t0 + k * 256;
        float4 ae, ce;
        ae.x = a[k].x + s[k].x; ae.y = a[k].y + s[k].y;
        ae.z = a[k].z + s[k].z; ae.w = a[k].w + s[k].w;
        ce.x = c[k].x + s[k].x; ce.y = c[k].y + s[k].y;
        ce.z = c[k].z + s[k].z; ce.w = c[k].w + s[k].w;
        ((float4*)g_He)[idx] = ae;
        ((float4*)g_Hc)[idx] = ce;
    }

    int gid = blockIdx.x * 256 + tid;
    if (gid < 11 * HDIM) {
        int r = gid / HDIM;
        int h = gid % HDIM;
        float w[11];
#pragma unroll
        for (int rp = 0; rp < 11; rp++) {
            float d = (float)(r - rp);
            int aa = rp - 5; if (aa < 0) aa = -aa;
            w[rp] = (float)(LSEQ - aa) * expf(-d * d);
        }
        float acc = b1[h];
        const float* w1row = W1 + h * W1COLS + 600;
#pragma unroll 2
        for (int d = 0; d < 50; d++) {
            float tv = 0.f;
#pragma unroll
            for (int rp = 0; rp < 11; rp++) tv += w[rp] * posW[rp * 50 + d];
            acc += tv * w1row[d];
        }
        g_T2[gid] = acc;
    }
}

// ---------------- 3-stage cp.async pipelined tf32 GEMM (R9 known-good) ----------------
#define GBM 128
#define GBN 64
#define GBK 16
#define KSTR 20
#define NIT 19
#define NSTG 3

__device__ __forceinline__ void cp_async16(uint32_t dst, const void* src, int src_bytes) {
    asm volatile("cp.async.cg.shared.global [%0], [%1], 16, %2;\n"
                 :: "r"(dst), "l"(src), "r"(src_bytes));
}
__device__ __forceinline__ void cp_async8(uint32_t dst, const void* src, int src_bytes) {
    asm volatile("cp.async.ca.shared.global [%0], [%1], 8, %2;\n"
                 :: "r"(dst), "l"(src), "r"(src_bytes));
}

__global__ __launch_bounds__(256) void gemm_tf32_kernel(const float* __restrict__ W1)
{
    __shared__ __align__(16) float As[NSTG][GBM][KSTR];
    __shared__ __align__(16) float Bs[NSTG][GBN][KSTR];

    const int z = blockIdx.z;
    const float* X = z ? g_Hc : g_He;
    const int off = z ? 300 : 0;
    float* Out = z ? g_C : g_A;

    const int m0 = blockIdx.y * GBM;
    const int n0 = blockIdx.x * GBN;
    const int tid = threadIdx.x;
    const int warp = tid >> 5;
    const int lane = tid & 31;
    const int wm = (warp & 3) * 32;
    const int wn = (warp >> 2) * 32;
    const int lq = lane >> 2;
    const int lr = lane & 3;

    const int arow = tid >> 2;
    const int ak   = (tid & 3) * 4;
    const int brow = tid >> 3;
    const int bk   = 2 * (tid & 7);

    const float* aSrc0 = X + (m0 + arow) * HDIM + ak;
    const float* aSrc1 = X + (m0 + arow + 64) * HDIM + ak;
    const float* bSrc0 = W1 + (n0 + brow) * W1COLS + off + bk;
    const float* bSrc1 = W1 + (n0 + brow + 32) * W1COLS + off + bk;
    const bool bOk0 = (n0 + brow) < HDIM;
    const bool bOk1 = (n0 + brow + 32) < HDIM;

    const uint32_t aD0 = (uint32_t)__cvta_generic_to_shared(&As[0][arow][ak]);
    const uint32_t aD1 = (uint32_t)__cvta_generic_to_shared(&As[0][arow + 64][ak]);
    const uint32_t bD0 = (uint32_t)__cvta_generic_to_shared(&Bs[0][brow][bk]);
    const uint32_t bD1 = (uint32_t)__cvta_generic_to_shared(&Bs[0][brow + 32][bk]);
    const uint32_t aBufSz = GBM * KSTR * 4;
    const uint32_t bBufSz = GBN * KSTR * 4;

    float acc[2][4][4];
#pragma unroll
    for (int a = 0; a < 2; a++)
#pragma unroll
        for (int b = 0; b < 4; b++)
#pragma unroll
            for (int c = 0; c < 4; c++) acc[a][b][c] = 0.f;

    auto issue = [&](int stage, int k0) {
        int asz = ((k0 + ak) < HDIM) ? 16 : 0;
        cp_async16(aD0 + stage * aBufSz, aSrc0 + k0, asz);
        cp_async16(aD1 + stage * aBufSz, aSrc1 + k0, asz);
        bool kOk = (k0 + bk) < HDIM;
        cp_async8(bD0 + stage * bBufSz, bSrc0 + k0, (bOk0 && kOk) ? 8 : 0);
        cp_async8(bD1 + stage * bBufSz, bSrc1 + k0, (bOk1 && kOk) ? 8 : 0);
    };

    issue(0, 0);
    asm volatile("cp.async.commit_group;\n" ::: "memory");
    issue(1, GBK);
    asm volatile("cp.async.commit_group;\n" ::: "memory");

    int buf = 0;
    for (int it = 0; it < NIT; it++) {
        asm volatile("cp.async.wait_group 1;\n" ::: "memory");
        __syncthreads();

        int nx = it + 2;
        if (nx < NIT) issue(nx % NSTG, nx * GBK);
        asm volatile("cp.async.commit_group;\n" ::: "memory");

#pragma unroll
        for (int s = 0; s < 2; s++) {
            const int kb = s * 8 + lr;
            unsigned af[2][4];
#pragma unroll
            for (int mf = 0; mf < 2; mf++) {
                const int mrow = wm + mf * 16 + lq;
                af[mf][0] = __float_as_uint(As[buf][mrow][kb]);
                af[mf][1] = __float_as_uint(As[buf][mrow + 8][kb]);
                af[mf][2] = __float_as_uint(As[buf][mrow][kb + 4]);
                af[mf][3] = __float_as_uint(As[buf][mrow + 8][kb + 4]);
            }
            unsigned bf[4][2];
#pragma unroll
            for (int nf = 0; nf < 4; nf++) {
                const int nrow = wn + nf * 8 + lq;
                bf[nf][0] = __float_as_uint(Bs[buf][nrow][kb]);
                bf[nf][1] = __float_as_uint(Bs[buf][nrow][kb + 4]);
            }
#pragma unroll
            for (int mf = 0; mf < 2; mf++)
#pragma unroll
                for (int nf = 0; nf < 4; nf++) {
                    asm volatile(
                        "mma.sync.aligned.m16n8k8.row.col.f32.tf32.tf32.f32 "
                        "{%0,%1,%2,%3}, {%4,%5,%6,%7}, {%8,%9}, {%0,%1,%2,%3};\n"
                        : "+f"(acc[mf][nf][0]), "+f"(acc[mf][nf][1]),
                          "+f"(acc[mf][nf][2]), "+f"(acc[mf][nf][3])
                        : "r"(af[mf][0]), "r"(af[mf][1]), "r"(af[mf][2]), "r"(af[mf][3]),
                          "r"(bf[nf][0]), "r"(bf[nf][1]));
                }
        }
        buf = (buf + 1 == NSTG) ? 0 : buf + 1;
    }

#pragma unroll
    for (int mf = 0; mf < 2; mf++) {
        const int row = m0 + wm + mf * 16 + lq;
#pragma unroll
        for (int nf = 0; nf < 4; nf++) {
            const int col = n0 + wn + nf * 8 + 2 * lr;
            if (col < HDIM) {
                *(float2*)&Out[row * HDIM + col] =
                    make_float2(acc[mf][nf][0], acc[mf][nf][1]);
                *(float2*)&Out[(row + 8) * HDIM + col] =
                    make_float2(acc[mf][nf][2], acc[mf][nf][3]);
            }
        }
    }
}

// ---------------- epilogue v5: i-tiled, 16-lane segments, packed f32x2, x in regs ----
#define CHI 8

__device__ __forceinline__ int band_off(int i) {
    if (i <= 1019) return (i < 5) ? (i * i + 11 * i) / 2 : 11 * i - 15;
    int s = i - 1019;
    return 11194 + 10 * s - s * (s - 1) / 2;
}

__global__ __launch_bounds__(256) void epi_kernel(
    const float* __restrict__ lng, const float* __restrict__ lnb,
    const float* __restrict__ W2, const float* __restrict__ b2,
    float* __restrict__ out, int write_pos)
{
    __shared__ __align__(16) float s_g[304];
    __shared__ __align__(16) float s_b[304];
    __shared__ __align__(16) float s_w[304];
    __shared__ __align__(16) float sT2[11 * HDIM];
    __shared__ __align__(16) float sA[CHI * HDIM];
    __shared__ __align__(16) float sC[(CHI + 10) * HDIM];

    const int tid = threadIdx.x;
    const int i0 = blockIdx.x * CHI;
    const int b = blockIdx.y;

    for (int h = tid; h < HDIM; h += 256) {
        s_g[h] = lng[h]; s_b[h] = lnb[h]; s_w[h] = W2[h];
    }
    for (int q = tid; q < 11 * HDIM / 4; q += 256)
        ((float4*)sT2)[q] = ((const float4*)g_T2)[q];
    {
        const float4* src = (const float4*)(g_A + (b * LSEQ + i0) * HDIM);
        float4* dst = (float4*)sA;
        for (int q = tid; q < CHI * (HDIM / 4); q += 256) dst[q] = src[q];
    }
    const int j0c = (i0 - 5 < 0) ? 0 : i0 - 5;
    const int j1c = (i0 + CHI + 4 > LSEQ - 1) ? LSEQ - 1 : i0 + CHI + 4;
    const int ncr = j1c - j0c + 1;
    {
        const float4* src = (const float4*)(g_C + (b * LSEQ + j0c) * HDIM);
        float4* dst = (float4*)sC;
        for (int q = tid; q < ncr * (HDIM / 4); q += 256) dst[q] = src[q];
    }
    __syncthreads();

    const int warp = tid >> 5;
    const int lane = tid & 31;
    const int half = lane >> 4;
    const int l16 = lane & 15;
    const float bias = __ldg(b2);
    const float inv = 1.f / (float)HDIM;

    for (int it = 0; it < 6; it++) {
        int p = it * 16 + warp * 2 + half;
        bool pv = (p < 88);
        int pc = pv ? p : 0;
        int i_off = pc / 11;
        int rel = pc - i_off * 11 - 5;
        int i = i0 + i_off;
        int j = i + rel;
        pv = pv && (j >= 0) && (j < LSEQ);

        const ulonglong2* a4 = (const ulonglong2*)(sA + i_off * HDIM);
        const ulonglong2* c4 = (const ulonglong2*)(sC + (pv ? (j - j0c) : 0) * HDIM);
        const ulonglong2* t4 = (const ulonglong2*)(sT2 + (rel + 5) * HDIM);

        ulonglong2 v[5];
        uint64_t s1p = 0ull, s2p = 0ull;   // bit pattern 0 == (0.f, 0.f)
#pragma unroll
        for (int q = 0; q < 5; q++) {
            int f = q * 16 + l16;
            if (f < 75) {
                ulonglong2 a = a4[f], c = c4[f], t = t4[f];
                uint64_t x0 = addx2(addx2(a.x, c.x), t.x);
                uint64_t x1 = addx2(addx2(a.y, c.y), t.y);
                v[q].x = x0; v[q].y = x1;
                s1p = addx2(s1p, addx2(x0, x1));
                s2p = fmax2(x0, x0, s2p);
                s2p = fmax2(x1, x1, s2p);
            } else {
                v[q].x = 0ull; v[q].y = 0ull;
            }
        }
        float s1a, s1b, s2a, s2b;
        f2up(s1p, s1a, s1b); f2up(s2p, s2a, s2b);
        float s1 = s1a + s1b, s2 = s2a + s2b;
#pragma unroll
        for (int o = 8; o; o >>= 1) {
            s1 += __shfl_xor_sync(0xffffffffu, s1, o);
            s2 += __shfl_xor_sync(0xffffffffu, s2, o);
        }
        float mu = s1 * inv;
        float var = s2 * inv - mu * mu;
        float rstd = rsqrtf(var + 1e-5f);
        uint64_t rp = f2pk(rstd, rstd);
        uint64_t mp = f2pk(-mu * rstd, -mu * rstd);

        float dot = 0.f;
#pragma unroll
        for (int q = 0; q < 5; q++) {
            int f = q * 16 + l16;
            if (f < 75) {
                ulonglong2 g = ((const ulonglong2*)s_g)[f];
                ulonglong2 bb = ((const ulonglong2*)s_b)[f];
                float4 w = ((const float4*)s_w)[f];
                uint64_t u0 = fmax2(v[q].x, rp, mp);   // (x-mu)*rstd
                uint64_t u1 = fmax2(v[q].y, rp, mp);
                uint64_t y0 = fmax2(u0, g.x, bb.x);    // *g + b
                uint64_t y1 = fmax2(u1, g.y, bb.y);
                float e0, e1, e2, e3;
                f2up(y0, e0, e1); f2up(y1, e2, e3);
                e0 = (e0 > 0.f) ? e0 : (__expf(e0) - 1.f);
                e1 = (e1 > 0.f) ? e1 : (__expf(e1) - 1.f);
                e2 = (e2 > 0.f) ? e2 : (__expf(e2) - 1.f);
                e3 = (e3 > 0.f) ? e3 : (__expf(e3) - 1.f);
                dot += e0 * w.x + e1 * w.y + e2 * w.z + e3 * w.w;
            }
        }
#pragma unroll
        for (int o = 8; o; o >>= 1) dot += __shfl_xor_sync(0xffffffffu, dot, o);

        if (pv && l16 == 0) {
            int jlo = (i - 5 < 0) ? 0 : i - 5;
            int oidx = band_off(i) + (j - jlo);
            out[b * NC + oidx] = dot + bias;
            if (write_pos && b == 0) {
                out[NPAIR + 2 * oidx]     = (float)(i + 1);
                out[NPAIR + 2 * oidx + 1] = (float)(j + 1);
            }
        }
    }
}

// ---------------- launcher ----------------
extern "C" void kernel_launch(void* const* d_in, const int* in_sizes, int n_in,
                              void* d_out, int out_size) {
    const float* h_e     = (const float*)d_in[0];
    const float* h_c     = (const float*)d_in[1];
    const float* h_share = (const float*)d_in[2];
    const float* pos_W   = (const float*)d_in[4];
    const float* W1      = (const float*)d_in[5];
    const float* b1      = (const float*)d_in[6];
    const float* ln_g    = (const float*)d_in[7];
    const float* ln_b    = (const float*)d_in[8];
    const float* W2      = (const float*)d_in[9];
    const float* b2      = (const float*)d_in[10];
    float* out = (float*)d_out;

    prep_kernel<<<1200, 256>>>(h_e, h_c, h_share, pos_W, W1, b1);

    dim3 ggrid((HDIM + GBN - 1) / GBN, (BATCH * LSEQ) / GBM, 2);
    gemm_tf32_kernel<<<ggrid, 256>>>(W1);

    int write_pos = (out_size >= NPAIR + 2 * NC) ? 1 : 0;
    dim3 egrid(LSEQ / CHI, BATCH);
    epi_kernel<<<egrid, 256>>>(ln_g, ln_b, W2, b2, out, write_pos);
}

// round 12
// speedup vs baseline: 1.6441x; 1.2930x over previous
#include <cuda_runtime.h>
#include <cuda_fp16.h>
#include <math.h>
#include <stdint.h>

#define LSEQ 1024
#define BATCH 8
#define HDIM 300
#define NC 11234
#define W1COLS 650
#define NPAIR (BATCH * NC)
#define KPAD 320                    // padded K (halves), zero-filled 300..319

// ---------------- device scratch ----------------
__device__ __align__(16) float  g_A[BATCH * LSEQ * HDIM];
__device__ __align__(16) float  g_C[BATCH * LSEQ * HDIM];
__device__ __align__(16) __half g_He[BATCH * LSEQ * KPAD];
__device__ __align__(16) __half g_Hc[BATCH * LSEQ * KPAD];
__device__ __align__(16) __half g_W1h[2 * KPAD * KPAD];   // [z][n][k], rows/k padded w/ zeros
__device__ __align__(16) float  g_T2[11 * HDIM];

// ---------------- packed f32x2 helpers (epi) ----------------
__device__ __forceinline__ uint64_t f2pk(float lo, float hi) {
    uint64_t r; asm("mov.b64 %0,{%1,%2};" : "=l"(r) : "f"(lo), "f"(hi)); return r;
}
__device__ __forceinline__ void f2up(uint64_t v, float& lo, float& hi) {
    asm("mov.b64 {%0,%1},%2;" : "=f"(lo), "=f"(hi) : "l"(v));
}
__device__ __forceinline__ uint64_t addx2(uint64_t a, uint64_t b) {
    uint64_t r; asm("add.rn.f32x2 %0,%1,%2;" : "=l"(r) : "l"(a), "l"(b)); return r;
}
__device__ __forceinline__ uint64_t fmax2(uint64_t a, uint64_t b, uint64_t c) {
    uint64_t r; asm("fma.rn.f32x2 %0,%1,%2,%3;" : "=l"(r) : "l"(a), "l"(b), "l"(c)); return r;
}

__device__ __forceinline__ unsigned pkh2(float a, float b) {
    __half2 h = __floats2half2_rn(a, b);
    return *reinterpret_cast<unsigned*>(&h);
}

// ---------------- prep: fp16 staging of He/Hc/W1 slices + T2 table ----------------
// blocks [0,1280): He/Hc chunks; [1280,1380): W1h; [1380,1393): T2
__global__ __launch_bounds__(256) void prep_kernel(
    const float* __restrict__ h_e, const float* __restrict__ h_c,
    const float* __restrict__ h_share,
    const float* __restrict__ posW, const float* __restrict__ W1,
    const float* __restrict__ b1)
{
    const int bid = blockIdx.x;
    const int tid = threadIdx.x;

    if (bid < 1280) {
        // one 16B (8-half) output chunk per thread for He and Hc
        const int task = bid * 256 + tid;          // 0..327679
        const int m = task / 40;
        const int ck = task - m * 40;
        const int kb = ck * 8;
        uint4 outE = make_uint4(0, 0, 0, 0);
        uint4 outC = make_uint4(0, 0, 0, 0);
        if (ck <= 37) {
            const int base = m * HDIM + kb;
            float4 s0 = *(const float4*)&h_share[base];
            float4 e0 = *(const float4*)&h_e[base];
            float4 c0 = *(const float4*)&h_c[base];
            float4 s1 = make_float4(0.f, 0.f, 0.f, 0.f);
            float4 e1 = s1, c1 = s1;
            if (ck <= 36) {
                s1 = *(const float4*)&h_share[base + 4];
                e1 = *(const float4*)&h_e[base + 4];
                c1 = *(const float4*)&h_c[base + 4];
            }
            outE.x = pkh2(e0.x + s0.x, e0.y + s0.y);
            outE.y = pkh2(e0.z + s0.z, e0.w + s0.w);
            outE.z = pkh2(e1.x + s1.x, e1.y + s1.y);
            outE.w = pkh2(e1.z + s1.z, e1.w + s1.w);
            outC.x = pkh2(c0.x + s0.x, c0.y + s0.y);
            outC.y = pkh2(c0.z + s0.z, c0.w + s0.w);
            outC.z = pkh2(c1.x + s1.x, c1.y + s1.y);
            outC.w = pkh2(c1.z + s1.z, c1.w + s1.w);
        }
        *(uint4*)&g_He[m * KPAD + kb] = outE;
        *(uint4*)&g_Hc[m * KPAD + kb] = outC;
    } else if (bid < 1380) {
        const int task = (bid - 1280) * 256 + tid;   // 0..25599
        const int z = task / 12800;
        const int rem = task - z * 12800;
        const int n = rem / 40;
        const int ck = rem - n * 40;
        unsigned h[4] = {0u, 0u, 0u, 0u};
        if (n < HDIM && ck <= 37) {
            const float* src = W1 + n * W1COLS + z * 300 + ck * 8;
            float v[8];
#pragma unroll
            for (int e = 0; e < 8; e++) {
                int k = ck * 8 + e;
                v[e] = (k < HDIM) ? src[e] : 0.f;
            }
            h[0] = pkh2(v[0], v[1]); h[1] = pkh2(v[2], v[3]);
            h[2] = pkh2(v[4], v[5]); h[3] = pkh2(v[6], v[7]);
        }
        *(uint4*)&g_W1h[(z * KPAD + n) * KPAD + ck * 8] =
            make_uint4(h[0], h[1], h[2], h[3]);
    } else {
        const int gid = (bid - 1380) * 256 + tid;
        if (gid < 11 * HDIM) {
            int r = gid / HDIM;
            int hh = gid - r * HDIM;
            float w[11];
#pragma unroll
            for (int rp = 0; rp < 11; rp++) {
                float d = (float)(r - rp);
                int aa = rp - 5; if (aa < 0) aa = -aa;
                w[rp] = (float)(LSEQ - aa) * expf(-d * d);
            }
            float acc = b1[hh];
            const float* w1row = W1 + hh * W1COLS + 600;
#pragma unroll 2
            for (int d = 0; d < 50; d++) {
                float tv = 0.f;
#pragma unroll
                for (int rp = 0; rp < 11; rp++) tv += w[rp] * posW[rp * 50 + d];
                acc += tv * w1row[d];
            }
            g_T2[gid] = acc;
        }
    }
}

// ---------------- fp16 3-stage cp.async pipelined GEMM ----------------
// mma.m16n8k16.f16, K tile = 32 halves, NIT = 10 (K padded to 320, zero-filled)
#define GBM 128
#define GBN 64
#define GBK 32
#define KSTRH 40      // smem row stride in halves (80B)
#define NIT 10
#define NSTG 3

__device__ __forceinline__ void cp_async16(uint32_t dst, const void* src) {
    asm volatile("cp.async.cg.shared.global [%0], [%1], 16;\n"
                 :: "r"(dst), "l"(src));
}

__global__ __launch_bounds__(256) void gemm_f16_kernel()
{
    __shared__ __align__(16) __half As[NSTG][GBM][KSTRH];  // 30720 B
    __shared__ __align__(16) __half Bs[NSTG][GBN][KSTRH];  // 15360 B

    const int z = blockIdx.z;
    const __half* X = z ? g_Hc : g_He;
    const __half* Wz = g_W1h + z * KPAD * KPAD;
    float* Out = z ? g_C : g_A;

    const int m0 = blockIdx.y * GBM;
    const int n0 = blockIdx.x * GBN;
    const int tid = threadIdx.x;
    const int warp = tid >> 5;
    const int lane = tid & 31;
    const int wm = (warp & 3) * 32;
    const int wn = (warp >> 2) * 32;
    const int lq = lane >> 2;
    const int lr = lane & 3;

    // copy geometry: A tile 128 rows x 32 halves = 512 x 16B chunks (2/thread)
    //                B tile 64 rows x 32 halves = 256 chunks (1/thread)
    const int arow = tid >> 2;
    const int ac   = (tid & 3) * 8;   // half offset within tile
    const int brow = tid >> 2;
    const int bc   = (tid & 3) * 8;

    const __half* aSrc0 = X + (m0 + arow) * KPAD + ac;
    const __half* aSrc1 = X + (m0 + arow + 64) * KPAD + ac;
    const __half* bSrc0 = Wz + (n0 + brow) * KPAD + bc;

    const uint32_t aD0 = (uint32_t)__cvta_generic_to_shared(&As[0][arow][ac]);
    const uint32_t aD1 = (uint32_t)__cvta_generic_to_shared(&As[0][arow + 64][ac]);
    const uint32_t bD0 = (uint32_t)__cvta_generic_to_shared(&Bs[0][brow][bc]);
    const uint32_t aBufSz = GBM * KSTRH * 2;   // 10240
    const uint32_t bBufSz = GBN * KSTRH * 2;   // 5120

    float acc[2][4][4];
#pragma unroll
    for (int a = 0; a < 2; a++)
#pragma unroll
        for (int b = 0; b < 4; b++)
#pragma unroll
            for (int c = 0; c < 4; c++) acc[a][b][c] = 0.f;

    auto issue = [&](int stage, int k0) {   // k0 in halves; always in-bounds (padded)
        cp_async16(aD0 + stage * aBufSz, aSrc0 + k0);
        cp_async16(aD1 + stage * aBufSz, aSrc1 + k0);
        cp_async16(bD0 + stage * bBufSz, bSrc0 + k0);
    };

    issue(0, 0);
    asm volatile("cp.async.commit_group;\n" ::: "memory");
    issue(1, GBK);
    asm volatile("cp.async.commit_group;\n" ::: "memory");

    int buf = 0;
    for (int it = 0; it < NIT; it++) {
        asm volatile("cp.async.wait_group 1;\n" ::: "memory");
        __syncthreads();

        int nx = it + 2;
        if (nx < NIT) issue(nx % NSTG, nx * GBK);
        asm volatile("cp.async.commit_group;\n" ::: "memory");

#pragma unroll
        for (int ks = 0; ks < 2; ks++) {
            const int kh = ks * 16 + lr * 2;
            unsigned af[2][4];
#pragma unroll
            for (int mf = 0; mf < 2; mf++) {
                const int mrow = wm + mf * 16 + lq;
                af[mf][0] = *(const unsigned*)&As[buf][mrow][kh];
                af[mf][1] = *(const unsigned*)&As[buf][mrow + 8][kh];
                af[mf][2] = *(const unsigned*)&As[buf][mrow][kh + 8];
                af[mf][3] = *(const unsigned*)&As[buf][mrow + 8][kh + 8];
            }
            unsigned bf[4][2];
#pragma unroll
            for (int nf = 0; nf < 4; nf++) {
                const int nrow = wn + nf * 8 + lq;
                bf[nf][0] = *(const unsigned*)&Bs[buf][nrow][kh];
                bf[nf][1] = *(const unsigned*)&Bs[buf][nrow][kh + 8];
            }
#pragma unroll
            for (int mf = 0; mf < 2; mf++)
#pragma unroll
                for (int nf = 0; nf < 4; nf++) {
                    asm volatile(
                        "mma.sync.aligned.m16n8k16.row.col.f32.f16.f16.f32 "
                        "{%0,%1,%2,%3}, {%4,%5,%6,%7}, {%8,%9}, {%0,%1,%2,%3};\n"
                        : "+f"(acc[mf][nf][0]), "+f"(acc[mf][nf][1]),
                          "+f"(acc[mf][nf][2]), "+f"(acc[mf][nf][3])
                        : "r"(af[mf][0]), "r"(af[mf][1]), "r"(af[mf][2]), "r"(af[mf][3]),
                          "r"(bf[nf][0]), "r"(bf[nf][1]));
                }
        }
        buf = (buf + 1 == NSTG) ? 0 : buf + 1;
    }

#pragma unroll
    for (int mf = 0; mf < 2; mf++) {
        const int row = m0 + wm + mf * 16 + lq;
#pragma unroll
        for (int nf = 0; nf < 4; nf++) {
            const int col = n0 + wn + nf * 8 + 2 * lr;
            if (col < HDIM) {
                *(float2*)&Out[row * HDIM + col] =
                    make_float2(acc[mf][nf][0], acc[mf][nf][1]);
                *(float2*)&Out[(row + 8) * HDIM + col] =
                    make_float2(acc[mf][nf][2], acc[mf][nf][3]);
            }
        }
    }
}

// ---------------- epilogue v5 (R11 known-good) ----------------
#define CHI 8

__device__ __forceinline__ int band_off(int i) {
    if (i <= 1019) return (i < 5) ? (i * i + 11 * i) / 2 : 11 * i - 15;
    int s = i - 1019;
    return 11194 + 10 * s - s * (s - 1) / 2;
}

__global__ __launch_bounds__(256) void epi_kernel(
    const float* __restrict__ lng, const float* __restrict__ lnb,
    const float* __restrict__ W2, const float* __restrict__ b2,
    float* __restrict__ out, int write_pos)
{
    __shared__ __align__(16) float s_g[304];
    __shared__ __align__(16) float s_b[304];
    __shared__ __align__(16) float s_w[304];
    __shared__ __align__(16) float sT2[11 * HDIM];
    __shared__ __align__(16) float sA[CHI * HDIM];
    __shared__ __align__(16) float sC[(CHI + 10) * HDIM];

    const int tid = threadIdx.x;
    const int i0 = blockIdx.x * CHI;
    const int b = blockIdx.y;

    for (int h = tid; h < HDIM; h += 256) {
        s_g[h] = lng[h]; s_b[h] = lnb[h]; s_w[h] = W2[h];
    }
    for (int q = tid; q < 11 * HDIM / 4; q += 256)
        ((float4*)sT2)[q] = ((const float4*)g_T2)[q];
    {
        const float4* src = (const float4*)(g_A + (b * LSEQ + i0) * HDIM);
        float4* dst = (float4*)sA;
        for (int q = tid; q < CHI * (HDIM / 4); q += 256) dst[q] = src[q];
    }
    const int j0c = (i0 - 5 < 0) ? 0 : i0 - 5;
    const int j1c = (i0 + CHI + 4 > LSEQ - 1) ? LSEQ - 1 : i0 + CHI + 4;
    const int ncr = j1c - j0c + 1;
    {
        const float4* src = (const float4*)(g_C + (b * LSEQ + j0c) * HDIM);
        float4* dst = (float4*)sC;
        for (int q = tid; q < ncr * (HDIM / 4); q += 256) dst[q] = src[q];
    }
    __syncthreads();

    const int warp = tid >> 5;
    const int lane = tid & 31;
    const int half = lane >> 4;
    const int l16 = lane & 15;
    const float bias = __ldg(b2);
    const float inv = 1.f / (float)HDIM;

    for (int it = 0; it < 6; it++) {
        int p = it * 16 + warp * 2 + half;
        bool pv = (p < 88);
        int pc = pv ? p : 0;
        int i_off = pc / 11;
        int rel = pc - i_off * 11 - 5;
        int i = i0 + i_off;
        int j = i + rel;
        pv = pv && (j >= 0) && (j < LSEQ);

        const ulonglong2* a4 = (const ulonglong2*)(sA + i_off * HDIM);
        const ulonglong2* c4 = (const ulonglong2*)(sC + (pv ? (j - j0c) : 0) * HDIM);
        const ulonglong2* t4 = (const ulonglong2*)(sT2 + (rel + 5) * HDIM);

        ulonglong2 v[5];
        uint64_t s1p = 0ull, s2p = 0ull;
#pragma unroll
        for (int q = 0; q < 5; q++) {
            int f = q * 16 + l16;
            if (f < 75) {
                ulonglong2 a = a4[f], c = c4[f], t = t4[f];
                uint64_t x0 = addx2(addx2(a.x, c.x), t.x);
                uint64_t x1 = addx2(addx2(a.y, c.y), t.y);
                v[q].x = x0; v[q].y = x1;
                s1p = addx2(s1p, addx2(x0, x1));
                s2p = fmax2(x0, x0, s2p);
                s2p = fmax2(x1, x1, s2p);
            } else {
                v[q].x = 0ull; v[q].y = 0ull;
            }
        }
        float s1a, s1b, s2a, s2b;
        f2up(s1p, s1a, s1b); f2up(s2p, s2a, s2b);
        float s1 = s1a + s1b, s2 = s2a + s2b;
#pragma unroll
        for (int o = 8; o; o >>= 1) {
            s1 += __shfl_xor_sync(0xffffffffu, s1, o);
            s2 += __shfl_xor_sync(0xffffffffu, s2, o);
        }
        float mu = s1 * inv;
        float var = s2 * inv - mu * mu;
        float rstd = rsqrtf(var + 1e-5f);
        uint64_t rp = f2pk(rstd, rstd);
        uint64_t mp = f2pk(-mu * rstd, -mu * rstd);

        float dot = 0.f;
#pragma unroll
        for (int q = 0; q < 5; q++) {
            int f = q * 16 + l16;
            if (f < 75) {
                ulonglong2 g = ((const ulonglong2*)s_g)[f];
                ulonglong2 bb = ((const ulonglong2*)s_b)[f];
                float4 w = ((const float4*)s_w)[f];
                uint64_t u0 = fmax2(v[q].x, rp, mp);
                uint64_t u1 = fmax2(v[q].y, rp, mp);
                uint64_t y0 = fmax2(u0, g.x, bb.x);
                uint64_t y1 = fmax2(u1, g.y, bb.y);
                float e0, e1, e2, e3;
                f2up(y0, e0, e1); f2up(y1, e2, e3);
                e0 = (e0 > 0.f) ? e0 : (__expf(e0) - 1.f);
                e1 = (e1 > 0.f) ? e1 : (__expf(e1) - 1.f);
                e2 = (e2 > 0.f) ? e2 : (__expf(e2) - 1.f);
                e3 = (e3 > 0.f) ? e3 : (__expf(e3) - 1.f);
                dot += e0 * w.x + e1 * w.y + e2 * w.z + e3 * w.w;
            }
        }
#pragma unroll
        for (int o = 8; o; o >>= 1) dot += __shfl_xor_sync(0xffffffffu, dot, o);

        if (pv && l16 == 0) {
            int jlo = (i - 5 < 0) ? 0 : i - 5;
            int oidx = band_off(i) + (j - jlo);
            out[b * NC + oidx] = dot + bias;
            if (write_pos && b == 0) {
                out[NPAIR + 2 * oidx]     = (float)(i + 1);
                out[NPAIR + 2 * oidx + 1] = (float)(j + 1);
            }
        }
    }
}

// ---------------- launcher ----------------
extern "C" void kernel_launch(void* const* d_in, const int* in_sizes, int n_in,
                              void* d_out, int out_size) {
    const float* h_e     = (const float*)d_in[0];
    const float* h_c     = (const float*)d_in[1];
    const float* h_share = (const float*)d_in[2];
    const float* pos_W   = (const float*)d_in[4];
    const float* W1      = (const float*)d_in[5];
    const float* b1      = (const float*)d_in[6];
    const float* ln_g    = (const float*)d_in[7];
    const float* ln_b    = (const float*)d_in[8];
    const float* W2      = (const float*)d_in[9];
    const float* b2      = (const float*)d_in[10];
    float* out = (float*)d_out;

    prep_kernel<<<1393, 256>>>(h_e, h_c, h_share, pos_W, W1, b1);

    dim3 ggrid((HDIM + GBN - 1) / GBN, (BATCH * LSEQ) / GBM, 2);
    gemm_f16_kernel<<<ggrid, 256>>>();

    int write_pos = (out_size >= NPAIR + 2 * NC) ? 1 : 0;
    dim3 egrid(LSEQ / CHI, BATCH);
    epi_kernel<<<egrid, 256>>>(ln_g, ln_b, W2, b2, out, write_pos);
}